// round 1
// baseline (speedup 1.0000x reference)
#include <cuda_runtime.h>
#include <math.h>

#define NMAX 250000
#define GMAX 8192

// Scratch (device globals — no allocation allowed)
__device__ float    g_h0[NMAX * 64];
__device__ float    g_h1[NMAX * 64];
__device__ float    g_h2[NMAX * 16];
__device__ float    g_gate[NMAX];
__device__ float    g_expv[NMAX];
__device__ unsigned g_gmax[GMAX];
__device__ float    g_gsum[GMAX];
__device__ float    g_emb[GMAX * 16];
__device__ float    g_tot;

// order-preserving float<->uint encoding for atomicMax on signed floats
__device__ __forceinline__ unsigned fenc(float f) {
    unsigned u = __float_as_uint(f);
    return (u & 0x80000000u) ? ~u : (u | 0x80000000u);
}
__device__ __forceinline__ float fdec(unsigned u) {
    return (u & 0x80000000u) ? __uint_as_float(u & 0x7fffffffu) : __uint_as_float(~u);
}

__global__ void k_init(int G) {
    int i = blockIdx.x * blockDim.x + threadIdx.x;
    if (i < G * 16) g_emb[i] = 0.f;
    if (i < G) { g_gmax[i] = 0u; g_gsum[i] = 0.f; }
    if (i == 0) g_tot = 0.f;
}

__global__ void k_embed(const int* __restrict__ x, const float* __restrict__ emb, int N) {
    int i = blockIdx.x * blockDim.x + threadIdx.x;
    if (i < N * 64) {
        int n = i >> 6, d = i & 63;
        g_h0[i] = emb[x[n] * 64 + d];
    }
}

// h1[n] = tanh(h0[n] @ W(64x64) + b)
__global__ void k_root64(const float* __restrict__ W, const float* __restrict__ b, int N) {
    __shared__ float Ws[64 * 64];
    __shared__ float bs[64];
    for (int i = threadIdx.x; i < 64 * 64; i += blockDim.x) Ws[i] = W[i];
    if (threadIdx.x < 64) bs[threadIdx.x] = b[threadIdx.x];
    __syncthreads();
    int i = blockIdx.x * blockDim.x + threadIdx.x;
    if (i >= N * 64) return;
    int n = i >> 6, j = i & 63;
    float acc = bs[j];
    const float* h = &g_h0[n * 64];
#pragma unroll
    for (int k = 0; k < 64; k++) acc = fmaf(h[k], Ws[k * 64 + j], acc);
    g_h1[i] = tanhf(acc);
}

// h2[n] = tanh(h1[n] @ W(64x16) + b)
__global__ void k_root16(const float* __restrict__ W, const float* __restrict__ b, int N) {
    __shared__ float Ws[64 * 16];
    __shared__ float bs[16];
    for (int i = threadIdx.x; i < 64 * 16; i += blockDim.x) Ws[i] = W[i];
    if (threadIdx.x < 16) bs[threadIdx.x] = b[threadIdx.x];
    __syncthreads();
    int i = blockIdx.x * blockDim.x + threadIdx.x;
    if (i >= N * 16) return;
    int n = i >> 4, j = i & 15;
    float acc = bs[j];
    const float* h = &g_h1[n * 64];
#pragma unroll
    for (int k = 0; k < 64; k++) acc = fmaf(h[k], Ws[k * 16 + j], acc);
    g_h2[i] = tanhf(acc);
}

// edge conv1: msg = tanh([h0[src], ea[e]] @ W(70x64) + b); atomicAdd into h1[dst]
__global__ void k_edge1(const int* __restrict__ ei, const float* __restrict__ ea,
                        const float* __restrict__ W, const float* __restrict__ b, int E) {
    __shared__ float Ws[70 * 64];
    __shared__ float bs[64];
    for (int i = threadIdx.x; i < 70 * 64; i += blockDim.x) Ws[i] = W[i];
    if (threadIdx.x < 64) bs[threadIdx.x] = b[threadIdx.x];
    __syncthreads();
    int lane = threadIdx.x & 31;
    int gw = (blockIdx.x * blockDim.x + threadIdx.x) >> 5;
    int nw = (gridDim.x * blockDim.x) >> 5;
    for (int e = gw; e < E; e += nw) {
        int dst = ei[e], src = ei[E + e];
        float a0 = g_h0[src * 64 + lane];
        float a1 = g_h0[src * 64 + 32 + lane];
        float acc0 = bs[lane], acc1 = bs[32 + lane];
#pragma unroll
        for (int k = 0; k < 32; k++) {
            float v = __shfl_sync(0xffffffffu, a0, k);
            acc0 = fmaf(v, Ws[k * 64 + lane], acc0);
            acc1 = fmaf(v, Ws[k * 64 + 32 + lane], acc1);
        }
#pragma unroll
        for (int k = 0; k < 32; k++) {
            float v = __shfl_sync(0xffffffffu, a1, k);
            acc0 = fmaf(v, Ws[(k + 32) * 64 + lane], acc0);
            acc1 = fmaf(v, Ws[(k + 32) * 64 + 32 + lane], acc1);
        }
        float eav = (lane < 6) ? ea[e * 6 + lane] : 0.f;
#pragma unroll
        for (int k = 0; k < 6; k++) {
            float v = __shfl_sync(0xffffffffu, eav, k);
            acc0 = fmaf(v, Ws[(64 + k) * 64 + lane], acc0);
            acc1 = fmaf(v, Ws[(64 + k) * 64 + 32 + lane], acc1);
        }
        atomicAdd(&g_h1[dst * 64 + lane], tanhf(acc0));
        atomicAdd(&g_h1[dst * 64 + 32 + lane], tanhf(acc1));
    }
}

// edge conv2: msg = tanh([h1[src], ea[e]] @ W(70x16) + b); atomicAdd into h2[dst]
// two edges per warp (16 lanes each)
__global__ void k_edge2(const int* __restrict__ ei, const float* __restrict__ ea,
                        const float* __restrict__ W, const float* __restrict__ b, int E) {
    __shared__ float Ws[70 * 16];
    __shared__ float bs[16];
    for (int i = threadIdx.x; i < 70 * 16; i += blockDim.x) Ws[i] = W[i];
    if (threadIdx.x < 16) bs[threadIdx.x] = b[threadIdx.x];
    __syncthreads();
    int lane = threadIdx.x & 31;
    int sub = lane >> 4;
    int j = lane & 15;
    int gw = (blockIdx.x * blockDim.x + threadIdx.x) >> 5;
    int nw = (gridDim.x * blockDim.x) >> 5;
    for (int p = gw; p * 2 < E; p += nw) {
        int e = p * 2 + sub;
        bool ok = (e < E);
        int ee = ok ? e : 0;
        int dst = ei[ee], src = ei[E + ee];
        float a0 = g_h1[src * 64 + j];
        float a1 = g_h1[src * 64 + 16 + j];
        float a2 = g_h1[src * 64 + 32 + j];
        float a3 = g_h1[src * 64 + 48 + j];
        float acc = bs[j];
#pragma unroll
        for (int k = 0; k < 16; k++) {
            float v = __shfl_sync(0xffffffffu, a0, k, 16);
            acc = fmaf(v, Ws[k * 16 + j], acc);
        }
#pragma unroll
        for (int k = 0; k < 16; k++) {
            float v = __shfl_sync(0xffffffffu, a1, k, 16);
            acc = fmaf(v, Ws[(16 + k) * 16 + j], acc);
        }
#pragma unroll
        for (int k = 0; k < 16; k++) {
            float v = __shfl_sync(0xffffffffu, a2, k, 16);
            acc = fmaf(v, Ws[(32 + k) * 16 + j], acc);
        }
#pragma unroll
        for (int k = 0; k < 16; k++) {
            float v = __shfl_sync(0xffffffffu, a3, k, 16);
            acc = fmaf(v, Ws[(48 + k) * 16 + j], acc);
        }
        float eav = (j < 6) ? ea[ee * 6 + j] : 0.f;
#pragma unroll
        for (int k = 0; k < 6; k++) {
            float v = __shfl_sync(0xffffffffu, eav, k, 16);
            acc = fmaf(v, Ws[(64 + k) * 16 + j], acc);
        }
        if (ok) atomicAdd(&g_h2[dst * 16 + j], tanhf(acc));
    }
}

// gate MLP 16->64->32->1 per node (warp per node); seg-max + total sum
__global__ void k_gate(const int* __restrict__ batch,
                       const float* __restrict__ Wg1, const float* __restrict__ bg1,
                       const float* __restrict__ Wg2, const float* __restrict__ bg2,
                       const float* __restrict__ Wg3, const float* __restrict__ bg3, int N) {
    __shared__ float W1s[16 * 64], b1s[64], W2s[64 * 32], b2s[32], W3s[32];
    __shared__ float b3s;
    for (int i = threadIdx.x; i < 16 * 64; i += blockDim.x) W1s[i] = Wg1[i];
    for (int i = threadIdx.x; i < 64 * 32; i += blockDim.x) W2s[i] = Wg2[i];
    if (threadIdx.x < 64) b1s[threadIdx.x] = bg1[threadIdx.x];
    if (threadIdx.x < 32) { b2s[threadIdx.x] = bg2[threadIdx.x]; W3s[threadIdx.x] = Wg3[threadIdx.x]; }
    if (threadIdx.x == 0) b3s = bg3[0];
    __syncthreads();
    int lane = threadIdx.x & 31;
    int gw = (blockIdx.x * blockDim.x + threadIdx.x) >> 5;
    int nw = (gridDim.x * blockDim.x) >> 5;
    for (int n = gw; n < N; n += nw) {
        float hv = (lane < 16) ? g_h2[n * 16 + lane] : 0.f;
        float acc0 = b1s[lane], acc1 = b1s[32 + lane];
#pragma unroll
        for (int k = 0; k < 16; k++) {
            float v = __shfl_sync(0xffffffffu, hv, k);
            acc0 = fmaf(v, W1s[k * 64 + lane], acc0);
            acc1 = fmaf(v, W1s[k * 64 + 32 + lane], acc1);
        }
        acc0 = fmaxf(acc0, 0.f);
        acc1 = fmaxf(acc1, 0.f);
        float g2 = b2s[lane];
#pragma unroll
        for (int k = 0; k < 32; k++) {
            float v = __shfl_sync(0xffffffffu, acc0, k);
            g2 = fmaf(v, W2s[k * 32 + lane], g2);
        }
#pragma unroll
        for (int k = 0; k < 32; k++) {
            float v = __shfl_sync(0xffffffffu, acc1, k);
            g2 = fmaf(v, W2s[(32 + k) * 32 + lane], g2);
        }
        g2 = fmaxf(g2, 0.f);
        float p = g2 * W3s[lane];
#pragma unroll
        for (int o = 16; o > 0; o >>= 1) p += __shfl_down_sync(0xffffffffu, p, o);
        if (lane == 0) {
            float gate = p + b3s;
            g_gate[n] = gate;
            atomicMax(&g_gmax[batch[n]], fenc(gate));
            atomicAdd(&g_tot, gate);
        }
    }
}

__global__ void k_expsum(const int* __restrict__ batch, float* __restrict__ att, int N) {
    int n = blockIdx.x * blockDim.x + threadIdx.x;
    if (n >= N) return;
    int b = batch[n];
    float m = fdec(g_gmax[b]);
    float e = expf(g_gate[n] - m);
    g_expv[n] = e;
    atomicAdd(&g_gsum[b], e);
    att[n] = g_gate[n] - g_tot / (float)N;
}

__global__ void k_scatter(const int* __restrict__ batch, int N) {
    int i = blockIdx.x * blockDim.x + threadIdx.x;
    if (i >= N * 16) return;
    int n = i >> 4, j = i & 15;
    int b = batch[n];
    float coef = g_expv[n] / (g_gsum[b] + 1e-16f);
    atomicAdd(&g_emb[b * 16 + j], coef * g_h2[n * 16 + j]);
}

__global__ void k_final(const float* __restrict__ Wsemi,
                        const float* __restrict__ gamma, const float* __restrict__ beta,
                        const float* __restrict__ mean, const float* __restrict__ var,
                        const float* __restrict__ Wf, const float* __restrict__ bf,
                        float* __restrict__ out, float* __restrict__ outsig,
                        float* __restrict__ out1, int G) {
    __shared__ float es[16];
    __shared__ float red[256];
    int g = blockIdx.x;
    int t = threadIdx.x;
    if (t < 16) es[t] = g_emb[g * 16 + t];
    __syncthreads();
    float p = 0.f;
    if (t < 200) {
        float acc = 0.f;
#pragma unroll
        for (int k = 0; k < 16; k++) acc = fmaf(es[k], Wsemi[k * 200 + t], acc);
        float v = (acc - mean[t]) * rsqrtf(var[t] + 1e-5f) * gamma[t] + beta[t];
        out1[g * 200 + t] = v;
        p = v * Wf[t];
    }
    red[t] = p;
    __syncthreads();
    for (int o = 128; o > 0; o >>= 1) {
        if (t < o) red[t] += red[t + o];
        __syncthreads();
    }
    if (t == 0) {
        float o = red[0] + bf[0];
        out[g] = o;
        outsig[g] = 1.f / (1.f + expf(-o));
    }
}

extern "C" void kernel_launch(void* const* d_in, const int* in_sizes, int n_in,
                              void* d_out, int out_size) {
    int N = in_sizes[0];
    int E = in_sizes[1] / 2;
    // num_graphs may appear as a scalar input at index 4 (size 1); embeds is 1536
    int off = (n_in > 4 && in_sizes[4] == 1) ? 1 : 0;

    const int*   x      = (const int*)d_in[0];
    const int*   ei     = (const int*)d_in[1];
    const float* ea     = (const float*)d_in[2];
    const int*   batch  = (const int*)d_in[3];
    const float* embeds = (const float*)d_in[4 + off];
    const float* Wn1 = (const float*)d_in[5 + off];  const float* bn1 = (const float*)d_in[6 + off];
    const float* Wr1 = (const float*)d_in[7 + off];  const float* br1 = (const float*)d_in[8 + off];
    const float* Wn2 = (const float*)d_in[9 + off];  const float* bn2 = (const float*)d_in[10 + off];
    const float* Wr2 = (const float*)d_in[11 + off]; const float* br2 = (const float*)d_in[12 + off];
    const float* Wg1 = (const float*)d_in[13 + off]; const float* bg1 = (const float*)d_in[14 + off];
    const float* Wg2 = (const float*)d_in[15 + off]; const float* bg2 = (const float*)d_in[16 + off];
    const float* Wg3 = (const float*)d_in[17 + off]; const float* bg3 = (const float*)d_in[18 + off];
    const float* Wsemi = (const float*)d_in[19 + off];
    const float* gamma = (const float*)d_in[20 + off];
    const float* beta  = (const float*)d_in[21 + off];
    const float* mean  = (const float*)d_in[22 + off];
    const float* var   = (const float*)d_in[23 + off];
    const float* Wf    = (const float*)d_in[24 + off];
    const float* bf    = (const float*)d_in[25 + off];

    int G = (out_size - N) / 202;  // out(G) + sig(G) + att(N) + out_1(G*200)
    float* outp  = (float*)d_out;
    float* sigp  = outp + G;
    float* attp  = outp + 2 * G;
    float* out1p = outp + 2 * G + N;

    k_init<<<(G * 16 + 255) / 256, 256>>>(G);
    k_embed<<<(N * 64 + 255) / 256, 256>>>(x, embeds, N);
    k_root64<<<(N * 64 + 255) / 256, 256>>>(Wr1, br1, N);
    k_edge1<<<2048, 256>>>(ei, ea, Wn1, bn1, E);
    k_root16<<<(N * 16 + 255) / 256, 256>>>(Wr2, br2, N);
    k_edge2<<<2048, 256>>>(ei, ea, Wn2, bn2, E);
    k_gate<<<1184, 256>>>(batch, Wg1, bg1, Wg2, bg2, Wg3, bg3, N);
    k_expsum<<<(N + 255) / 256, 256>>>(batch, attp, N);
    k_scatter<<<(N * 16 + 255) / 256, 256>>>(batch, N);
    k_final<<<G, 256>>>(Wsemi, gamma, beta, mean, var, Wf, bf, outp, sigp, out1p, G);
}

// round 2
// speedup vs baseline: 3.0281x; 3.0281x over previous
#include <cuda_runtime.h>
#include <math.h>

#define NMAX 250000
#define GMAX 8192

// Scratch (device globals — no allocation allowed)
__device__ float    g_h1[NMAX * 64];
__device__ float    g_h2[NMAX * 16];
__device__ float    g_gate[NMAX];
__device__ float    g_expv[NMAX];
__device__ unsigned g_gmax[GMAX];
__device__ float    g_gsum[GMAX];
__device__ float    g_emb[GMAX * 16];
__device__ float    g_tot;
__device__ float    g_R1[24 * 64];   // tanh(embeds @ W_root1 + b_root1)
__device__ float    g_P1[24 * 64];   // embeds @ W_neg1[0:64] + b_neg1

// order-preserving float<->uint encoding for atomicMax on signed floats
__device__ __forceinline__ unsigned fenc(float f) {
    unsigned u = __float_as_uint(f);
    return (u & 0x80000000u) ? ~u : (u | 0x80000000u);
}
__device__ __forceinline__ float fdec(unsigned u) {
    return (u & 0x80000000u) ? __uint_as_float(u & 0x7fffffffu) : __uint_as_float(~u);
}

__global__ void k_init(int G) {
    int i = blockIdx.x * blockDim.x + threadIdx.x;
    if (i < G * 16) g_emb[i] = 0.f;
    if (i < G) { g_gmax[i] = 0u; g_gsum[i] = 0.f; }
    if (i == 0) g_tot = 0.f;
}

// 24 blocks x 64 threads: per-embedding-row tables for conv1
__global__ void k_tables(const float* __restrict__ emb,
                         const float* __restrict__ Wr1, const float* __restrict__ br1,
                         const float* __restrict__ Wn1, const float* __restrict__ bn1) {
    int i = blockIdx.x;       // embed row 0..23
    int j = threadIdx.x;      // col 0..63
    float accR = br1[j], accP = bn1[j];
#pragma unroll
    for (int k = 0; k < 64; k++) {
        float e = emb[i * 64 + k];
        accR = fmaf(e, Wr1[k * 64 + j], accR);
        accP = fmaf(e, Wn1[k * 64 + j], accP);
    }
    g_R1[i * 64 + j] = tanhf(accR);
    g_P1[i * 64 + j] = accP;
}

// h1[n] = R1[x[n]]  (root part of conv1; edge messages atomically added later)
__global__ void k_h1init(const int* __restrict__ x, int N) {
    int i = blockIdx.x * blockDim.x + threadIdx.x;
    if (i < N * 64) {
        int n = i >> 6, d = i & 63;
        g_h1[i] = g_R1[x[n] * 64 + d];
    }
}

// conv1 edges: msg = tanh(P1[x[src]] + ea @ We + bias-in-P1); atomicAdd into h1[dst]
__global__ void k_edge1(const int* __restrict__ ei, const float* __restrict__ ea,
                        const float* __restrict__ Wn1, const int* __restrict__ x, int E) {
    __shared__ float P1s[24 * 64];  // 6 KB
    __shared__ float We[6 * 64];    // edge-attr weight rows
    for (int i = threadIdx.x; i < 24 * 64; i += blockDim.x) P1s[i] = g_P1[i];
    for (int i = threadIdx.x; i < 6 * 64; i += blockDim.x) We[i] = Wn1[64 * 64 + i];
    __syncthreads();
    int lane = threadIdx.x & 31;
    int gw = (blockIdx.x * blockDim.x + threadIdx.x) >> 5;
    int nw = (gridDim.x * blockDim.x) >> 5;
    for (int e = gw; e < E; e += nw) {
        int dst = ei[e], src = ei[E + e];
        int xi = x[src];
        float ev = (lane < 6) ? ea[e * 6 + lane] : 0.f;
        float acc0 = P1s[xi * 64 + lane];
        float acc1 = P1s[xi * 64 + 32 + lane];
#pragma unroll
        for (int k = 0; k < 6; k++) {
            float v = __shfl_sync(0xffffffffu, ev, k);
            acc0 = fmaf(v, We[k * 64 + lane], acc0);
            acc1 = fmaf(v, We[k * 64 + 32 + lane], acc1);
        }
        atomicAdd(&g_h1[dst * 64 + lane], tanhf(acc0));
        atomicAdd(&g_h1[dst * 64 + 32 + lane], tanhf(acc1));
    }
}

// h2[n] = tanh(h1[n] @ W(64x16) + b)   (warp handles 2 nodes, 16 lanes each)
__global__ void k_root16(const float* __restrict__ W, const float* __restrict__ b, int N) {
    __shared__ float Ws[64 * 16];
    __shared__ float bs[16];
    for (int i = threadIdx.x; i < 64 * 16; i += blockDim.x) Ws[i] = W[i];
    if (threadIdx.x < 16) bs[threadIdx.x] = b[threadIdx.x];
    __syncthreads();
    int lane = threadIdx.x & 31;
    int sub = lane >> 4;
    int j = lane & 15;
    int gw = (blockIdx.x * blockDim.x + threadIdx.x) >> 5;
    int nw = (gridDim.x * blockDim.x) >> 5;
    for (int p = gw; p * 2 < N; p += nw) {
        int n = p * 2 + sub;
        bool ok = (n < N);
        int nn = ok ? n : 0;
        float a0 = g_h1[nn * 64 + j];
        float a1 = g_h1[nn * 64 + 16 + j];
        float a2 = g_h1[nn * 64 + 32 + j];
        float a3 = g_h1[nn * 64 + 48 + j];
        float acc = bs[j];
#pragma unroll
        for (int k = 0; k < 16; k++) {
            float w0 = Ws[k * 16 + j];
            acc = fmaf(__shfl_sync(0xffffffffu, a0, k, 16), w0, acc);
        }
#pragma unroll
        for (int k = 0; k < 16; k++) {
            float w0 = Ws[(16 + k) * 16 + j];
            acc = fmaf(__shfl_sync(0xffffffffu, a1, k, 16), w0, acc);
        }
#pragma unroll
        for (int k = 0; k < 16; k++) {
            float w0 = Ws[(32 + k) * 16 + j];
            acc = fmaf(__shfl_sync(0xffffffffu, a2, k, 16), w0, acc);
        }
#pragma unroll
        for (int k = 0; k < 16; k++) {
            float w0 = Ws[(48 + k) * 16 + j];
            acc = fmaf(__shfl_sync(0xffffffffu, a3, k, 16), w0, acc);
        }
        if (ok) g_h2[nn * 16 + j] = tanhf(acc);
    }
}

// conv2 edges: msg = tanh([h1[src], ea] @ W(70x16) + b); atomicAdd into h2[dst]
// 4 edges per warp-iteration (2 sub-halves x 2 batched), weight LDS reused
__global__ void k_edge2(const int* __restrict__ ei, const float* __restrict__ ea,
                        const float* __restrict__ W, const float* __restrict__ b, int E) {
    __shared__ float Ws[70 * 16];
    __shared__ float bs[16];
    for (int i = threadIdx.x; i < 70 * 16; i += blockDim.x) Ws[i] = W[i];
    if (threadIdx.x < 16) bs[threadIdx.x] = b[threadIdx.x];
    __syncthreads();
    int lane = threadIdx.x & 31;
    int sub = lane >> 4;
    int j = lane & 15;
    int gw = (blockIdx.x * blockDim.x + threadIdx.x) >> 5;
    int nw = (gridDim.x * blockDim.x) >> 5;
    for (int p = gw; p * 4 < E; p += nw) {
        int e0 = p * 4 + sub;
        int e1 = p * 4 + 2 + sub;
        bool ok0 = (e0 < E), ok1 = (e1 < E);
        int ee0 = ok0 ? e0 : 0, ee1 = ok1 ? e1 : 0;
        int dst0 = ei[ee0], src0 = ei[E + ee0];
        int dst1 = ei[ee1], src1 = ei[E + ee1];
        float a00 = g_h1[src0 * 64 + j];
        float a01 = g_h1[src0 * 64 + 16 + j];
        float a02 = g_h1[src0 * 64 + 32 + j];
        float a03 = g_h1[src0 * 64 + 48 + j];
        float a10 = g_h1[src1 * 64 + j];
        float a11 = g_h1[src1 * 64 + 16 + j];
        float a12 = g_h1[src1 * 64 + 32 + j];
        float a13 = g_h1[src1 * 64 + 48 + j];
        float ev0 = (j < 6) ? ea[ee0 * 6 + j] : 0.f;
        float ev1 = (j < 6) ? ea[ee1 * 6 + j] : 0.f;
        float acc0 = bs[j], acc1 = bs[j];
#pragma unroll
        for (int k = 0; k < 16; k++) {
            float w = Ws[k * 16 + j];
            acc0 = fmaf(__shfl_sync(0xffffffffu, a00, k, 16), w, acc0);
            acc1 = fmaf(__shfl_sync(0xffffffffu, a10, k, 16), w, acc1);
        }
#pragma unroll
        for (int k = 0; k < 16; k++) {
            float w = Ws[(16 + k) * 16 + j];
            acc0 = fmaf(__shfl_sync(0xffffffffu, a01, k, 16), w, acc0);
            acc1 = fmaf(__shfl_sync(0xffffffffu, a11, k, 16), w, acc1);
        }
#pragma unroll
        for (int k = 0; k < 16; k++) {
            float w = Ws[(32 + k) * 16 + j];
            acc0 = fmaf(__shfl_sync(0xffffffffu, a02, k, 16), w, acc0);
            acc1 = fmaf(__shfl_sync(0xffffffffu, a12, k, 16), w, acc1);
        }
#pragma unroll
        for (int k = 0; k < 16; k++) {
            float w = Ws[(48 + k) * 16 + j];
            acc0 = fmaf(__shfl_sync(0xffffffffu, a03, k, 16), w, acc0);
            acc1 = fmaf(__shfl_sync(0xffffffffu, a13, k, 16), w, acc1);
        }
#pragma unroll
        for (int k = 0; k < 6; k++) {
            float w = Ws[(64 + k) * 16 + j];
            acc0 = fmaf(__shfl_sync(0xffffffffu, ev0, k, 16), w, acc0);
            acc1 = fmaf(__shfl_sync(0xffffffffu, ev1, k, 16), w, acc1);
        }
        if (ok0) atomicAdd(&g_h2[dst0 * 16 + j], tanhf(acc0));
        if (ok1) atomicAdd(&g_h2[dst1 * 16 + j], tanhf(acc1));
    }
}

// gate MLP 16->64->32->1 per node (warp per node); seg-max + block-reduced total sum
__global__ void k_gate(const int* __restrict__ batch,
                       const float* __restrict__ Wg1, const float* __restrict__ bg1,
                       const float* __restrict__ Wg2, const float* __restrict__ bg2,
                       const float* __restrict__ Wg3, const float* __restrict__ bg3, int N) {
    __shared__ float W1s[16 * 64], b1s[64], W2s[64 * 32], b2s[32], W3s[32];
    __shared__ float b3s;
    __shared__ float red[256];
    for (int i = threadIdx.x; i < 16 * 64; i += blockDim.x) W1s[i] = Wg1[i];
    for (int i = threadIdx.x; i < 64 * 32; i += blockDim.x) W2s[i] = Wg2[i];
    if (threadIdx.x < 64) b1s[threadIdx.x] = bg1[threadIdx.x];
    if (threadIdx.x < 32) { b2s[threadIdx.x] = bg2[threadIdx.x]; W3s[threadIdx.x] = Wg3[threadIdx.x]; }
    if (threadIdx.x == 0) b3s = bg3[0];
    __syncthreads();
    int lane = threadIdx.x & 31;
    int gw = (blockIdx.x * blockDim.x + threadIdx.x) >> 5;
    int nw = (gridDim.x * blockDim.x) >> 5;
    float tloc = 0.f;
    for (int n = gw; n < N; n += nw) {
        float hv = (lane < 16) ? g_h2[n * 16 + lane] : 0.f;
        float acc0 = b1s[lane], acc1 = b1s[32 + lane];
#pragma unroll
        for (int k = 0; k < 16; k++) {
            float v = __shfl_sync(0xffffffffu, hv, k);
            acc0 = fmaf(v, W1s[k * 64 + lane], acc0);
            acc1 = fmaf(v, W1s[k * 64 + 32 + lane], acc1);
        }
        acc0 = fmaxf(acc0, 0.f);
        acc1 = fmaxf(acc1, 0.f);
        float g2 = b2s[lane];
#pragma unroll
        for (int k = 0; k < 32; k++) {
            float v = __shfl_sync(0xffffffffu, acc0, k);
            g2 = fmaf(v, W2s[k * 32 + lane], g2);
        }
#pragma unroll
        for (int k = 0; k < 32; k++) {
            float v = __shfl_sync(0xffffffffu, acc1, k);
            g2 = fmaf(v, W2s[(32 + k) * 32 + lane], g2);
        }
        g2 = fmaxf(g2, 0.f);
        float p = g2 * W3s[lane];
#pragma unroll
        for (int o = 16; o > 0; o >>= 1) p += __shfl_down_sync(0xffffffffu, p, o);
        if (lane == 0) {
            float gate = p + b3s;
            g_gate[n] = gate;
            atomicMax(&g_gmax[batch[n]], fenc(gate));
            tloc += gate;
        }
    }
    red[threadIdx.x] = tloc;
    __syncthreads();
    for (int o = 128; o > 0; o >>= 1) {
        if (threadIdx.x < o) red[threadIdx.x] += red[threadIdx.x + o];
        __syncthreads();
    }
    if (threadIdx.x == 0 && red[0] != 0.f) atomicAdd(&g_tot, red[0]);
    else if (threadIdx.x == 0) atomicAdd(&g_tot, red[0]);
}

__global__ void k_expsum(const int* __restrict__ batch, float* __restrict__ att, int N) {
    int n = blockIdx.x * blockDim.x + threadIdx.x;
    if (n >= N) return;
    int b = batch[n];
    float m = fdec(g_gmax[b]);
    float e = expf(g_gate[n] - m);
    g_expv[n] = e;
    atomicAdd(&g_gsum[b], e);
    att[n] = g_gate[n] - g_tot / (float)N;
}

__global__ void k_scatter(const int* __restrict__ batch, int N) {
    int i = blockIdx.x * blockDim.x + threadIdx.x;
    if (i >= N * 16) return;
    int n = i >> 4, j = i & 15;
    int b = batch[n];
    float coef = g_expv[n] / (g_gsum[b] + 1e-16f);
    atomicAdd(&g_emb[b * 16 + j], coef * g_h2[n * 16 + j]);
}

__global__ void k_final(const float* __restrict__ Wsemi,
                        const float* __restrict__ gamma, const float* __restrict__ beta,
                        const float* __restrict__ mean, const float* __restrict__ var,
                        const float* __restrict__ Wf, const float* __restrict__ bf,
                        float* __restrict__ out, float* __restrict__ outsig,
                        float* __restrict__ out1, int G) {
    __shared__ float es[16];
    __shared__ float red[256];
    int g = blockIdx.x;
    int t = threadIdx.x;
    if (t < 16) es[t] = g_emb[g * 16 + t];
    __syncthreads();
    float p = 0.f;
    if (t < 200) {
        float acc = 0.f;
#pragma unroll
        for (int k = 0; k < 16; k++) acc = fmaf(es[k], Wsemi[k * 200 + t], acc);
        float v = (acc - mean[t]) * rsqrtf(var[t] + 1e-5f) * gamma[t] + beta[t];
        out1[g * 200 + t] = v;
        p = v * Wf[t];
    }
    red[t] = p;
    __syncthreads();
    for (int o = 128; o > 0; o >>= 1) {
        if (t < o) red[t] += red[t + o];
        __syncthreads();
    }
    if (t == 0) {
        float o = red[0] + bf[0];
        out[g] = o;
        outsig[g] = 1.f / (1.f + expf(-o));
    }
}

extern "C" void kernel_launch(void* const* d_in, const int* in_sizes, int n_in,
                              void* d_out, int out_size) {
    int N = in_sizes[0];
    int E = in_sizes[1] / 2;
    int off = (n_in > 4 && in_sizes[4] == 1) ? 1 : 0;

    const int*   x      = (const int*)d_in[0];
    const int*   ei     = (const int*)d_in[1];
    const float* ea     = (const float*)d_in[2];
    const int*   batch  = (const int*)d_in[3];
    const float* embeds = (const float*)d_in[4 + off];
    const float* Wn1 = (const float*)d_in[5 + off];  const float* bn1 = (const float*)d_in[6 + off];
    const float* Wr1 = (const float*)d_in[7 + off];  const float* br1 = (const float*)d_in[8 + off];
    const float* Wn2 = (const float*)d_in[9 + off];  const float* bn2 = (const float*)d_in[10 + off];
    const float* Wr2 = (const float*)d_in[11 + off]; const float* br2 = (const float*)d_in[12 + off];
    const float* Wg1 = (const float*)d_in[13 + off]; const float* bg1 = (const float*)d_in[14 + off];
    const float* Wg2 = (const float*)d_in[15 + off]; const float* bg2 = (const float*)d_in[16 + off];
    const float* Wg3 = (const float*)d_in[17 + off]; const float* bg3 = (const float*)d_in[18 + off];
    const float* Wsemi = (const float*)d_in[19 + off];
    const float* gamma = (const float*)d_in[20 + off];
    const float* beta  = (const float*)d_in[21 + off];
    const float* mean  = (const float*)d_in[22 + off];
    const float* var   = (const float*)d_in[23 + off];
    const float* Wf    = (const float*)d_in[24 + off];
    const float* bf    = (const float*)d_in[25 + off];

    int G = (out_size - N) / 202;
    float* outp  = (float*)d_out;
    float* sigp  = outp + G;
    float* attp  = outp + 2 * G;
    float* out1p = outp + 2 * G + N;

    k_init<<<(G * 16 + 255) / 256, 256>>>(G);
    k_tables<<<24, 64>>>(embeds, Wr1, br1, Wn1, bn1);
    k_h1init<<<(N * 64 + 255) / 256, 256>>>(x, N);
    k_edge1<<<2048, 256>>>(ei, ea, Wn1, x, E);
    k_root16<<<1184, 256>>>(Wr2, br2, N);
    k_edge2<<<2048, 256>>>(ei, ea, Wn2, bn2, E);
    k_gate<<<1184, 256>>>(batch, Wg1, bg1, Wg2, bg2, Wg3, bg3, N);
    k_expsum<<<(N + 255) / 256, 256>>>(batch, attp, N);
    k_scatter<<<(N * 16 + 255) / 256, 256>>>(batch, N);
    k_final<<<G, 256>>>(Wsemi, gamma, beta, mean, var, Wf, bf, outp, sigp, out1p, G);
}

// round 6
// speedup vs baseline: 5.4642x; 1.8045x over previous
#include <cuda_runtime.h>
#include <math.h>

#define NMAX 250000
#define GMAX 8192

// Scratch (device globals — no allocation allowed)
__device__ float    g_h1[NMAX * 64];
__device__ float    g_h2[NMAX * 16];
__device__ float    g_U2[NMAX * 16];   // h1 @ W_neg2[0:64] + b_neg2
__device__ float    g_gate[NMAX];
__device__ float    g_expv[NMAX];
__device__ unsigned g_gmax[GMAX];
__device__ float    g_gsum[GMAX];
__device__ float    g_emb[GMAX * 16];
__device__ float    g_tot;
__device__ float    g_R1[24 * 64];   // tanh(embeds @ W_root1 + b_root1)
__device__ float    g_P1[24 * 64];   // embeds @ W_neg1[0:64] + b_neg1

__device__ __forceinline__ unsigned fenc(float f) {
    unsigned u = __float_as_uint(f);
    return (u & 0x80000000u) ? ~u : (u | 0x80000000u);
}
__device__ __forceinline__ float fdec(unsigned u) {
    return (u & 0x80000000u) ? __uint_as_float(u & 0x7fffffffu) : __uint_as_float(~u);
}

// fast tanh: 1 - 2/(e^{2x}+1); saturates correctly for |x| large
__device__ __forceinline__ float tanh_fast(float x) {
    float t = __expf(2.f * x);
    return 1.f - __fdividef(2.f, t + 1.f);
}

__global__ void k_init(int G) {
    int i = blockIdx.x * blockDim.x + threadIdx.x;
    if (i < G * 16) g_emb[i] = 0.f;
    if (i < G) { g_gmax[i] = 0u; g_gsum[i] = 0.f; }
    if (i == 0) g_tot = 0.f;
}

// 24 blocks x 64 threads: per-embedding-row tables for conv1
__global__ void k_tables(const float* __restrict__ emb,
                         const float* __restrict__ Wr1, const float* __restrict__ br1,
                         const float* __restrict__ Wn1, const float* __restrict__ bn1) {
    int i = blockIdx.x;
    int j = threadIdx.x;
    float accR = br1[j], accP = bn1[j];
#pragma unroll
    for (int k = 0; k < 64; k++) {
        float e = emb[i * 64 + k];
        accR = fmaf(e, Wr1[k * 64 + j], accR);
        accP = fmaf(e, Wn1[k * 64 + j], accP);
    }
    g_R1[i * 64 + j] = tanhf(accR);   // tiny kernel: keep precise tanh
    g_P1[i * 64 + j] = accP;
}

// h1[n] = R1[x[n]]
__global__ void k_h1init(const int* __restrict__ x, int N) {
    int i = blockIdx.x * blockDim.x + threadIdx.x;
    if (i < N * 64) {
        int n = i >> 6, d = i & 63;
        g_h1[i] = g_R1[x[n] * 64 + d];
    }
}

// conv1 edges: msg = tanh(P1[x[src]] + ea @ We); atomicAdd into h1[dst]
// We (12 floats/lane) in registers; 2 edges per warp-iteration
__global__ void k_edge1(const int* __restrict__ ei, const float* __restrict__ ea,
                        const float* __restrict__ Wn1, const int* __restrict__ x, int E) {
    __shared__ float P1s[24 * 64];  // 6 KB
    for (int i = threadIdx.x; i < 24 * 64; i += blockDim.x) P1s[i] = g_P1[i];
    __syncthreads();
    int lane = threadIdx.x & 31;
    float w0[6], w1[6];
#pragma unroll
    for (int k = 0; k < 6; k++) {
        w0[k] = Wn1[(64 + k) * 64 + lane];
        w1[k] = Wn1[(64 + k) * 64 + 32 + lane];
    }
    int gw = (blockIdx.x * blockDim.x + threadIdx.x) >> 5;
    int nw = (gridDim.x * blockDim.x) >> 5;
    for (int p = gw; p * 2 < E; p += nw) {
        int e0 = p * 2;
        int e1 = p * 2 + 1;
        bool ok1 = (e1 < E);
        int ee1 = ok1 ? e1 : e0;
        int dst0 = ei[e0], src0 = ei[E + e0];
        int dst1 = ei[ee1], src1 = ei[E + ee1];
        int x0 = x[src0], x1 = x[src1];
        float ev0 = (lane < 6) ? ea[e0 * 6 + lane] : 0.f;
        float ev1 = (lane < 6) ? ea[ee1 * 6 + lane] : 0.f;
        float a00 = P1s[x0 * 64 + lane];
        float a01 = P1s[x0 * 64 + 32 + lane];
        float a10 = P1s[x1 * 64 + lane];
        float a11 = P1s[x1 * 64 + 32 + lane];
#pragma unroll
        for (int k = 0; k < 6; k++) {
            float v0 = __shfl_sync(0xffffffffu, ev0, k);
            float v1 = __shfl_sync(0xffffffffu, ev1, k);
            a00 = fmaf(v0, w0[k], a00);
            a01 = fmaf(v0, w1[k], a01);
            a10 = fmaf(v1, w0[k], a10);
            a11 = fmaf(v1, w1[k], a11);
        }
        atomicAdd(&g_h1[dst0 * 64 + lane], tanh_fast(a00));
        atomicAdd(&g_h1[dst0 * 64 + 32 + lane], tanh_fast(a01));
        if (ok1) {
            atomicAdd(&g_h1[dst1 * 64 + lane], tanh_fast(a10));
            atomicAdd(&g_h1[dst1 * 64 + 32 + lane], tanh_fast(a11));
        }
    }
}

// per-node: h2init[n] = tanh(h1[n]@Wr2+br2), U2[n] = h1[n]@Wn2[0:64]+bn2
// warp handles 2 nodes (16 lanes each); shfl shared between both outputs
__global__ void k_root16(const float* __restrict__ Wr, const float* __restrict__ br,
                         const float* __restrict__ Wn, const float* __restrict__ bn, int N) {
    __shared__ float Wrs[64 * 16];
    __shared__ float Wns[64 * 16];
    __shared__ float brs[16], bns[16];
    for (int i = threadIdx.x; i < 64 * 16; i += blockDim.x) { Wrs[i] = Wr[i]; Wns[i] = Wn[i]; }
    if (threadIdx.x < 16) { brs[threadIdx.x] = br[threadIdx.x]; bns[threadIdx.x] = bn[threadIdx.x]; }
    __syncthreads();
    int lane = threadIdx.x & 31;
    int sub = lane >> 4;
    int j = lane & 15;
    int gw = (blockIdx.x * blockDim.x + threadIdx.x) >> 5;
    int nw = (gridDim.x * blockDim.x) >> 5;
    for (int p = gw; p * 2 < N; p += nw) {
        int n = p * 2 + sub;
        bool ok = (n < N);
        int nn = ok ? n : 0;
        float a0 = g_h1[nn * 64 + j];
        float a1 = g_h1[nn * 64 + 16 + j];
        float a2 = g_h1[nn * 64 + 32 + j];
        float a3 = g_h1[nn * 64 + 48 + j];
        float accR = brs[j], accU = bns[j];
#pragma unroll
        for (int k = 0; k < 16; k++) {
            float v = __shfl_sync(0xffffffffu, a0, k, 16);
            accR = fmaf(v, Wrs[k * 16 + j], accR);
            accU = fmaf(v, Wns[k * 16 + j], accU);
        }
#pragma unroll
        for (int k = 0; k < 16; k++) {
            float v = __shfl_sync(0xffffffffu, a1, k, 16);
            accR = fmaf(v, Wrs[(16 + k) * 16 + j], accR);
            accU = fmaf(v, Wns[(16 + k) * 16 + j], accU);
        }
#pragma unroll
        for (int k = 0; k < 16; k++) {
            float v = __shfl_sync(0xffffffffu, a2, k, 16);
            accR = fmaf(v, Wrs[(32 + k) * 16 + j], accR);
            accU = fmaf(v, Wns[(32 + k) * 16 + j], accU);
        }
#pragma unroll
        for (int k = 0; k < 16; k++) {
            float v = __shfl_sync(0xffffffffu, a3, k, 16);
            accR = fmaf(v, Wrs[(48 + k) * 16 + j], accR);
            accU = fmaf(v, Wns[(48 + k) * 16 + j], accU);
        }
        if (ok) {
            g_h2[nn * 16 + j] = tanh_fast(accR);
            g_U2[nn * 16 + j] = accU;
        }
    }
}

// conv2 edges: msg = tanh(U2[src] + ea@We2); atomicAdd into h2[dst]
// half-warp per edge, 4 edges per warp-iteration, We2 in registers
__global__ void k_edge2(const int* __restrict__ ei, const float* __restrict__ ea,
                        const float* __restrict__ Wn2, int E) {
    int lane = threadIdx.x & 31;
    int sub = lane >> 4;
    int j = lane & 15;
    float w[6];
#pragma unroll
    for (int k = 0; k < 6; k++) w[k] = Wn2[(64 + k) * 16 + j];
    int gw = (blockIdx.x * blockDim.x + threadIdx.x) >> 5;
    int nw = (gridDim.x * blockDim.x) >> 5;
    for (int p = gw; p * 4 < E; p += nw) {
        int e0 = p * 4 + sub;
        int e1 = p * 4 + 2 + sub;
        bool ok0 = (e0 < E), ok1 = (e1 < E);
        int ee0 = ok0 ? e0 : 0, ee1 = ok1 ? e1 : 0;
        int dst0 = ei[ee0], src0 = ei[E + ee0];
        int dst1 = ei[ee1], src1 = ei[E + ee1];
        float acc0 = g_U2[src0 * 16 + j];
        float acc1 = g_U2[src1 * 16 + j];
        float ev0 = (j < 6) ? ea[ee0 * 6 + j] : 0.f;
        float ev1 = (j < 6) ? ea[ee1 * 6 + j] : 0.f;
#pragma unroll
        for (int k = 0; k < 6; k++) {
            float v0 = __shfl_sync(0xffffffffu, ev0, k, 16);
            float v1 = __shfl_sync(0xffffffffu, ev1, k, 16);
            acc0 = fmaf(v0, w[k], acc0);
            acc1 = fmaf(v1, w[k], acc1);
        }
        if (ok0) atomicAdd(&g_h2[dst0 * 16 + j], tanh_fast(acc0));
        if (ok1) atomicAdd(&g_h2[dst1 * 16 + j], tanh_fast(acc1));
    }
}

// gate MLP 16->64->32->1; warp handles 2 nodes; seg-max + block-reduced total
__global__ void k_gate(const int* __restrict__ batch,
                       const float* __restrict__ Wg1, const float* __restrict__ bg1,
                       const float* __restrict__ Wg2, const float* __restrict__ bg2,
                       const float* __restrict__ Wg3, const float* __restrict__ bg3, int N) {
    __shared__ float W1s[16 * 64], b1s[64], W2s[64 * 32], b2s[32], W3s[32];
    __shared__ float b3s;
    __shared__ float red[256];
    for (int i = threadIdx.x; i < 16 * 64; i += blockDim.x) W1s[i] = Wg1[i];
    for (int i = threadIdx.x; i < 64 * 32; i += blockDim.x) W2s[i] = Wg2[i];
    if (threadIdx.x < 64) b1s[threadIdx.x] = bg1[threadIdx.x];
    if (threadIdx.x < 32) { b2s[threadIdx.x] = bg2[threadIdx.x]; W3s[threadIdx.x] = Wg3[threadIdx.x]; }
    if (threadIdx.x == 0) b3s = bg3[0];
    __syncthreads();
    int lane = threadIdx.x & 31;
    int gw = (blockIdx.x * blockDim.x + threadIdx.x) >> 5;
    int nw = (gridDim.x * blockDim.x) >> 5;
    float tloc = 0.f;
    for (int p = gw; p * 2 < N; p += nw) {
        int n0 = p * 2;
        int n1 = p * 2 + 1;
        bool ok1 = (n1 < N);
        int nn1 = ok1 ? n1 : n0;
        float h0 = (lane < 16) ? g_h2[n0 * 16 + lane] : 0.f;
        float h1 = (lane < 16) ? g_h2[nn1 * 16 + lane] : 0.f;
        float a00 = b1s[lane], a01 = b1s[32 + lane];
        float a10 = a00, a11 = a01;
#pragma unroll
        for (int k = 0; k < 16; k++) {
            float wlo = W1s[k * 64 + lane];
            float whi = W1s[k * 64 + 32 + lane];
            float v0 = __shfl_sync(0xffffffffu, h0, k);
            float v1 = __shfl_sync(0xffffffffu, h1, k);
            a00 = fmaf(v0, wlo, a00);
            a01 = fmaf(v0, whi, a01);
            a10 = fmaf(v1, wlo, a10);
            a11 = fmaf(v1, whi, a11);
        }
        a00 = fmaxf(a00, 0.f); a01 = fmaxf(a01, 0.f);
        a10 = fmaxf(a10, 0.f); a11 = fmaxf(a11, 0.f);
        float g20 = b2s[lane], g21 = g20;
#pragma unroll
        for (int k = 0; k < 32; k++) {
            float w = W2s[k * 32 + lane];
            g20 = fmaf(__shfl_sync(0xffffffffu, a00, k), w, g20);
            g21 = fmaf(__shfl_sync(0xffffffffu, a10, k), w, g21);
        }
#pragma unroll
        for (int k = 0; k < 32; k++) {
            float w = W2s[(32 + k) * 32 + lane];
            g20 = fmaf(__shfl_sync(0xffffffffu, a01, k), w, g20);
            g21 = fmaf(__shfl_sync(0xffffffffu, a11, k), w, g21);
        }
        g20 = fmaxf(g20, 0.f);
        g21 = fmaxf(g21, 0.f);
        float w3 = W3s[lane];
        float p0 = g20 * w3;
        float p1 = g21 * w3;
#pragma unroll
        for (int o = 16; o > 0; o >>= 1) {
            p0 += __shfl_down_sync(0xffffffffu, p0, o);
            p1 += __shfl_down_sync(0xffffffffu, p1, o);
        }
        if (lane == 0) {
            float gate0 = p0 + b3s;
            g_gate[n0] = gate0;
            atomicMax(&g_gmax[batch[n0]], fenc(gate0));
            tloc += gate0;
            if (ok1) {
                float gate1 = p1 + b3s;
                g_gate[n1] = gate1;
                atomicMax(&g_gmax[batch[n1]], fenc(gate1));
                tloc += gate1;
            }
        }
    }
    red[threadIdx.x] = tloc;
    __syncthreads();
    for (int o = 128; o > 0; o >>= 1) {
        if (threadIdx.x < o) red[threadIdx.x] += red[threadIdx.x + o];
        __syncthreads();
    }
    if (threadIdx.x == 0) atomicAdd(&g_tot, red[0]);
}

__global__ void k_expsum(const int* __restrict__ batch, float* __restrict__ att, int N) {
    int n = blockIdx.x * blockDim.x + threadIdx.x;
    if (n >= N) return;
    int b = batch[n];
    float m = fdec(g_gmax[b]);
    float e = expf(g_gate[n] - m);
    g_expv[n] = e;
    atomicAdd(&g_gsum[b], e);
    att[n] = g_gate[n] - g_tot / (float)N;
}

__global__ void k_scatter(const int* __restrict__ batch, int N) {
    int i = blockIdx.x * blockDim.x + threadIdx.x;
    if (i >= N * 16) return;
    int n = i >> 4, j = i & 15;
    int b = batch[n];
    float coef = g_expv[n] / (g_gsum[b] + 1e-16f);
    atomicAdd(&g_emb[b * 16 + j], coef * g_h2[n * 16 + j]);
}

__global__ void k_final(const float* __restrict__ Wsemi,
                        const float* __restrict__ gamma, const float* __restrict__ beta,
                        const float* __restrict__ mean, const float* __restrict__ var,
                        const float* __restrict__ Wf, const float* __restrict__ bf,
                        float* __restrict__ out, float* __restrict__ outsig,
                        float* __restrict__ out1, int G) {
    __shared__ float es[16];
    __shared__ float red[256];
    int g = blockIdx.x;
    int t = threadIdx.x;
    if (t < 16) es[t] = g_emb[g * 16 + t];
    __syncthreads();
    float p = 0.f;
    if (t < 200) {
        float acc = 0.f;
#pragma unroll
        for (int k = 0; k < 16; k++) acc = fmaf(es[k], Wsemi[k * 200 + t], acc);
        float v = (acc - mean[t]) * rsqrtf(var[t] + 1e-5f) * gamma[t] + beta[t];
        out1[g * 200 + t] = v;
        p = v * Wf[t];
    }
    red[t] = p;
    __syncthreads();
    for (int o = 128; o > 0; o >>= 1) {
        if (t < o) red[t] += red[t + o];
        __syncthreads();
    }
    if (t == 0) {
        float o = red[0] + bf[0];
        out[g] = o;
        outsig[g] = 1.f / (1.f + expf(-o));
    }
}

extern "C" void kernel_launch(void* const* d_in, const int* in_sizes, int n_in,
                              void* d_out, int out_size) {
    int N = in_sizes[0];
    int E = in_sizes[1] / 2;
    int off = (n_in > 4 && in_sizes[4] == 1) ? 1 : 0;

    const int*   x      = (const int*)d_in[0];
    const int*   ei     = (const int*)d_in[1];
    const float* ea     = (const float*)d_in[2];
    const int*   batch  = (const int*)d_in[3];
    const float* embeds = (const float*)d_in[4 + off];
    const float* Wn1 = (const float*)d_in[5 + off];  const float* bn1 = (const float*)d_in[6 + off];
    const float* Wr1 = (const float*)d_in[7 + off];  const float* br1 = (const float*)d_in[8 + off];
    const float* Wn2 = (const float*)d_in[9 + off];  const float* bn2 = (const float*)d_in[10 + off];
    const float* Wr2 = (const float*)d_in[11 + off]; const float* br2 = (const float*)d_in[12 + off];
    const float* Wg1 = (const float*)d_in[13 + off]; const float* bg1 = (const float*)d_in[14 + off];
    const float* Wg2 = (const float*)d_in[15 + off]; const float* bg2 = (const float*)d_in[16 + off];
    const float* Wg3 = (const float*)d_in[17 + off]; const float* bg3 = (const float*)d_in[18 + off];
    const float* Wsemi = (const float*)d_in[19 + off];
    const float* gamma = (const float*)d_in[20 + off];
    const float* beta  = (const float*)d_in[21 + off];
    const float* mean  = (const float*)d_in[22 + off];
    const float* var   = (const float*)d_in[23 + off];
    const float* Wf    = (const float*)d_in[24 + off];
    const float* bf    = (const float*)d_in[25 + off];

    int G = (out_size - N) / 202;
    float* outp  = (float*)d_out;
    float* sigp  = outp + G;
    float* attp  = outp + 2 * G;
    float* out1p = outp + 2 * G + N;

    k_init<<<(G * 16 + 255) / 256, 256>>>(G);
    k_tables<<<24, 64>>>(embeds, Wr1, br1, Wn1, bn1);
    k_h1init<<<(N * 64 + 255) / 256, 256>>>(x, N);
    k_edge1<<<2368, 256>>>(ei, ea, Wn1, x, E);
    k_root16<<<1184, 256>>>(Wr2, br2, Wn2, bn2, N);
    k_edge2<<<2368, 256>>>(ei, ea, Wn2, E);
    k_gate<<<1184, 256>>>(batch, Wg1, bg1, Wg2, bg2, Wg3, bg3, N);
    k_expsum<<<(N + 255) / 256, 256>>>(batch, attp, N);
    k_scatter<<<(N * 16 + 255) / 256, 256>>>(batch, N);
    k_final<<<G, 256>>>(Wsemi, gamma, beta, mean, var, Wf, bf, outp, sigp, out1p, G);
}